// round 1
// baseline (speedup 1.0000x reference)
#include <cuda_runtime.h>
#include <math.h>

#define T_ 4
#define B_ 32
#define C_ 384
#define N_ 196
#define H_ 12
#define D_ 32
#define BCN (B_*C_*N_)      /* 2408448 */
#define TBCN (T_*BCN)       /* 9633792 */
#define M3 (3*C_)           /* 1152 */

// ---------------- scratch (device globals; no allocations) ----------------
__device__ float g_y[3*TBCN];          // qkv pre-activations  (~116MB)
__device__ unsigned char g_s[3*TBCN];  // qkv spikes (u8)      (~29MB)
__device__ unsigned char g_satt[TBCN]; // attention spikes     (~9.6MB)
__device__ float g_yp[TBCN];           // proj pre-activation  (~38.5MB)
__device__ float g_w[M3*C_];           // packed [q;k;v] weights
__device__ float g_bninv[4*C_];
__device__ float g_bnshift[4*C_];

// ---------------- prep: pack weights + fold BN ----------------
__global__ void prep_kernel(
    const float* __restrict__ qw, const float* __restrict__ kw, const float* __restrict__ vw,
    const float* __restrict__ qg, const float* __restrict__ qb, const float* __restrict__ qm, const float* __restrict__ qv,
    const float* __restrict__ kg, const float* __restrict__ kb, const float* __restrict__ km, const float* __restrict__ kvv,
    const float* __restrict__ vg, const float* __restrict__ vb, const float* __restrict__ vm, const float* __restrict__ vvv,
    const float* __restrict__ pg, const float* __restrict__ pb, const float* __restrict__ pm, const float* __restrict__ pv,
    const float* __restrict__ pbias)
{
    int idx = blockIdx.x * blockDim.x + threadIdx.x;
    if (idx < M3*C_) {
        int mg = idx / C_;
        int k  = idx - mg*C_;
        int p  = mg / C_;
        int o  = mg - p*C_;
        const float* w = (p==0) ? qw : (p==1) ? kw : vw;
        g_w[idx] = w[o*C_ + k];
    }
    if (idx < 4*C_) {
        int p = idx / C_, c = idx - (idx/C_)*C_;
        const float *G,*Bt,*Mn,*Vr; float bias = 0.f;
        if      (p==0){G=qg;Bt=qb;Mn=qm;Vr=qv;}
        else if (p==1){G=kg;Bt=kb;Mn=km;Vr=kvv;}
        else if (p==2){G=vg;Bt=vb;Mn=vm;Vr=vvv;}
        else          {G=pg;Bt=pb;Mn=pm;Vr=pv; bias=pbias[c];}
        float inv = G[c] / sqrtf(Vr[c] + 1e-5f);
        g_bninv[idx]   = inv;
        g_bnshift[idx] = Bt[c] + (bias - Mn[c]) * inv;
    }
}

// ---------------- GEMM: y = BN(W @ x) for q,k,v (M=1152) ----------------
// tile 64(M) x 98(N) x 16(K); 112 threads; thread tile 8x7
#define BM 64
#define BNN 98
#define BK 16

__global__ void gemm_qkv(const float* __restrict__ X)
{
    __shared__ float Ws[BK][BM];
    __shared__ float Xs[BK][BNN];
    int tid = threadIdx.x;
    int tx = tid % 14;        // n group
    int ty = tid / 14;        // m group (0..7)
    int bz = blockIdx.z;      // t*B + b
    int m0 = blockIdx.y * BM;
    int n0 = blockIdx.x * BNN;
    const float* Xb = X + (size_t)bz * (C_*N_);

    float acc[8][7];
#pragma unroll
    for (int i = 0; i < 8; i++)
#pragma unroll
        for (int j = 0; j < 7; j++) acc[i][j] = 0.f;

    for (int k0 = 0; k0 < C_; k0 += BK) {
        for (int i = tid; i < BM*BK; i += 112) {
            int ml = i >> 4, kk = i & 15;
            Ws[kk][ml] = g_w[(m0+ml)*C_ + k0 + kk];
        }
        for (int i = tid; i < BK*BNN; i += 112) {
            int kk = i / BNN, nl = i - kk*BNN;
            Xs[kk][nl] = Xb[(k0+kk)*N_ + n0 + nl];
        }
        __syncthreads();
#pragma unroll
        for (int kk = 0; kk < BK; kk++) {
            float a[8], bb[7];
#pragma unroll
            for (int i = 0; i < 8; i++) a[i] = Ws[kk][ty + 8*i];
#pragma unroll
            for (int j = 0; j < 7; j++) bb[j] = Xs[kk][tx + 14*j];
#pragma unroll
            for (int i = 0; i < 8; i++)
#pragma unroll
                for (int j = 0; j < 7; j++) acc[i][j] += a[i]*bb[j];
        }
        __syncthreads();
    }

    int t = bz >> 5, b = bz & 31;
#pragma unroll
    for (int i = 0; i < 8; i++) {
        int mg = m0 + ty + 8*i;
        int p  = mg / C_;
        int c  = mg - p*C_;
        float inv = g_bninv[mg], sh = g_bnshift[mg];
        float* out = g_y + (size_t)p*TBCN + (size_t)t*BCN + ((size_t)b*C_ + c)*N_ + n0;
#pragma unroll
        for (int j = 0; j < 7; j++) out[tx + 14*j] = acc[i][j]*inv + sh;
    }
}

// ---------------- GEMM: proj on u8 spikes (M=384) ----------------
__global__ void gemm_proj(const float* __restrict__ Wp)
{
    __shared__ float Ws[BK][BM];
    __shared__ float Xs[BK][BNN];
    int tid = threadIdx.x;
    int tx = tid % 14;
    int ty = tid / 14;
    int bz = blockIdx.z;
    int m0 = blockIdx.y * BM;
    int n0 = blockIdx.x * BNN;
    const unsigned char* Sb = g_satt + (size_t)bz * (C_*N_);

    float acc[8][7];
#pragma unroll
    for (int i = 0; i < 8; i++)
#pragma unroll
        for (int j = 0; j < 7; j++) acc[i][j] = 0.f;

    for (int k0 = 0; k0 < C_; k0 += BK) {
        for (int i = tid; i < BM*BK; i += 112) {
            int ml = i >> 4, kk = i & 15;
            Ws[kk][ml] = Wp[(m0+ml)*C_ + k0 + kk];
        }
        for (int i = tid; i < BK*BNN; i += 112) {
            int kk = i / BNN, nl = i - kk*BNN;
            Xs[kk][nl] = (float)Sb[(k0+kk)*N_ + n0 + nl];
        }
        __syncthreads();
#pragma unroll
        for (int kk = 0; kk < BK; kk++) {
            float a[8], bb[7];
#pragma unroll
            for (int i = 0; i < 8; i++) a[i] = Ws[kk][ty + 8*i];
#pragma unroll
            for (int j = 0; j < 7; j++) bb[j] = Xs[kk][tx + 14*j];
#pragma unroll
            for (int i = 0; i < 8; i++)
#pragma unroll
                for (int j = 0; j < 7; j++) acc[i][j] += a[i]*bb[j];
        }
        __syncthreads();
    }

#pragma unroll
    for (int i = 0; i < 8; i++) {
        int mg = m0 + ty + 8*i;  // channel (M=384)
        float inv = g_bninv[3*C_ + mg], sh = g_bnshift[3*C_ + mg];
        float* out = g_yp + (size_t)bz*(C_*N_) + (size_t)mg*N_ + n0;
#pragma unroll
        for (int j = 0; j < 7; j++) out[tx + 14*j] = acc[i][j]*inv + sh;
    }
}

// ---------------- LIF over t for qkv pre-activations -> u8 spikes ----------------
__global__ void lif_qkv()
{
    int idx = blockIdx.x * blockDim.x + threadIdx.x;
    if (idx >= 3*BCN) return;
    int p = idx / BCN;
    int r = idx - p*BCN;
    size_t base = (size_t)p*TBCN + r;
    float v = 0.f;
#pragma unroll
    for (int t = 0; t < T_; t++) {
        float x = g_y[base + (size_t)t*BCN];
        v = v + (x - v)*0.5f;
        unsigned char s = (v >= 1.0f) ? 1 : 0;
        g_s[base + (size_t)t*BCN] = s;
        if (s) v = 0.f;
    }
}

// ---------------- attention: per (b,h), all t; G-factorized; fused LIF(0.5) ----------------
// y[n,d] = 0.25*( sum_c Q[c,n]*G[c,d] + (1-p[n])*(Q[:,n].K[:,n])*V[d,n] )
// G[c,d] = sum_m K[c,m]*p[m]*V[d,m]
__global__ void attn_kernel(const float* __restrict__ policy)
{
    int h = blockIdx.x;  // 0..11
    int b = blockIdx.y;  // 0..31
    int tid = threadIdx.x; // 256

    __shared__ unsigned char Qs[32*196];
    __shared__ unsigned char Ks[32*196];
    __shared__ unsigned char VTs[196*32];   // transposed: [m][d]
    __shared__ float Gs[32*32];
    __shared__ float ps[196];
    __shared__ float dns[196];

    float vlif[32];
#pragma unroll
    for (int d = 0; d < 32; d++) vlif[d] = 0.f;

    for (int t = 0; t < T_; t++) {
        size_t base = (size_t)t*BCN + ((size_t)b*C_ + h*32)*N_;
        // loads (Q,K,V tiles are 32x196 contiguous)
        for (int i = tid; i < 32*196; i += 256) {
            Qs[i] = g_s[base + i];
            Ks[i] = g_s[(size_t)TBCN + base + i];
            int d = i / 196, m = i - d*196;
            VTs[m*32 + d] = g_s[2*(size_t)TBCN + base + i];
        }
        for (int i = tid; i < 196; i += 256)
            ps[i] = policy[(size_t)(t*B_ + b)*N_ + i];
        __syncthreads();

        // diag term: dns[n] = (1-p[n]) * popcount(Q[:,n]&K[:,n])
        if (tid < 196) {
            int n = tid, dd = 0;
#pragma unroll
            for (int c = 0; c < 32; c++) dd += (int)(Qs[c*196+n] & Ks[c*196+n]);
            dns[n] = (1.0f - ps[n]) * (float)dd;
        }

        // G: thread (c = tid&31, dg = tid>>5) computes G[c][4dg..4dg+3]
        {
            int c = tid & 31, dg = tid >> 5;
            float g0=0.f,g1=0.f,g2=0.f,g3=0.f;
            const unsigned char* Kc = Ks + c*196;
            const unsigned char* Vb = VTs + dg*4;
            for (int m = 0; m < 196; m++) {
                float kp = Kc[m] ? ps[m] : 0.0f;
                uchar4 v4 = *(const uchar4*)(Vb + m*32);
                g0 += v4.x ? kp : 0.0f;
                g1 += v4.y ? kp : 0.0f;
                g2 += v4.z ? kp : 0.0f;
                g3 += v4.w ? kp : 0.0f;
            }
            Gs[c*32 + dg*4 + 0] = g0;
            Gs[c*32 + dg*4 + 1] = g1;
            Gs[c*32 + dg*4 + 2] = g2;
            Gs[c*32 + dg*4 + 3] = g3;
        }
        __syncthreads();

        // Y + fused LIF(0.5): thread n owns all d
        if (tid < 196) {
            int n = tid;
            float acc[32];
#pragma unroll
            for (int d = 0; d < 32; d++) acc[d] = 0.f;
            const unsigned char* Qn = Qs + n;
#pragma unroll
            for (int c = 0; c < 32; c++) {
                float qf = (float)Qn[c*196];
                const float4* Gr = (const float4*)(Gs + c*32);
#pragma unroll
                for (int q4 = 0; q4 < 8; q4++) {
                    float4 g4 = Gr[q4];
                    acc[q4*4+0] += qf * g4.x;
                    acc[q4*4+1] += qf * g4.y;
                    acc[q4*4+2] += qf * g4.z;
                    acc[q4*4+3] += qf * g4.w;
                }
            }
            float dn = dns[n];
            const uchar4* Vn = (const uchar4*)(VTs + n*32);
#pragma unroll
            for (int q4 = 0; q4 < 8; q4++) {
                uchar4 v4 = Vn[q4];
                acc[q4*4+0] += v4.x ? dn : 0.0f;
                acc[q4*4+1] += v4.y ? dn : 0.0f;
                acc[q4*4+2] += v4.z ? dn : 0.0f;
                acc[q4*4+3] += v4.w ? dn : 0.0f;
            }
            size_t obase = (size_t)t*BCN + ((size_t)b*C_ + h*32)*N_ + n;
#pragma unroll
            for (int d = 0; d < 32; d++) {
                float y = 0.25f * acc[d];
                float v = vlif[d];
                v = v + (y - v)*0.5f;
                unsigned char s = (v >= 0.5f) ? 1 : 0;
                g_satt[obase + (size_t)d*N_] = s;
                vlif[d] = s ? 0.f : v;
            }
        }
        __syncthreads();
    }
}

// ---------------- final LIF(1.0) -> fp32 output ----------------
__global__ void lif_final(float* __restrict__ out)
{
    int idx = blockIdx.x * blockDim.x + threadIdx.x;
    if (idx >= BCN) return;
    float v = 0.f;
#pragma unroll
    for (int t = 0; t < T_; t++) {
        float x = g_yp[(size_t)t*BCN + idx];
        v = v + (x - v)*0.5f;
        float s = (v >= 1.0f) ? 1.f : 0.f;
        out[(size_t)t*BCN + idx] = s;
        if (s != 0.f) v = 0.f;
    }
}

// ---------------- launch ----------------
extern "C" void kernel_launch(void* const* d_in, const int* in_sizes, int n_in,
                              void* d_out, int out_size)
{
    const float* x      = (const float*)d_in[0];
    const float* policy = (const float*)d_in[1];
    const float* qw = (const float*)d_in[2];
    const float* qg = (const float*)d_in[3];
    const float* qb = (const float*)d_in[4];
    const float* qm = (const float*)d_in[5];
    const float* qv = (const float*)d_in[6];
    const float* kw = (const float*)d_in[7];
    const float* kg = (const float*)d_in[8];
    const float* kb = (const float*)d_in[9];
    const float* km = (const float*)d_in[10];
    const float* kv = (const float*)d_in[11];
    const float* vw = (const float*)d_in[12];
    const float* vg = (const float*)d_in[13];
    const float* vb = (const float*)d_in[14];
    const float* vm = (const float*)d_in[15];
    const float* vv = (const float*)d_in[16];
    const float* pw = (const float*)d_in[17];
    const float* pg = (const float*)d_in[18];
    const float* pb = (const float*)d_in[19];
    const float* pm = (const float*)d_in[20];
    const float* pv = (const float*)d_in[21];
    const float* pbias = (const float*)d_in[22];

    prep_kernel<<<(M3*C_ + 255)/256, 256>>>(qw,kw,vw, qg,qb,qm,qv, kg,kb,km,kv,
                                            vg,vb,vm,vv, pg,pb,pm,pv, pbias);
    gemm_qkv<<<dim3(2,18,128), 112>>>(x);
    lif_qkv<<<(3*BCN + 255)/256, 256>>>();
    attn_kernel<<<dim3(12,32), 256>>>(policy);
    gemm_proj<<<dim3(2,6,128), 112>>>(pw);
    lif_final<<<(BCN + 255)/256, 256>>>((float*)d_out);
}